// round 15
// baseline (speedup 1.0000x reference)
#include <cuda_runtime.h>
#include <math.h>

#define VOCAB 50257
#define BATCH 512
#define SEQ   512
#define EMBED 256
#define OUTC  5
#define EV4   (EMBED / 4)   // 64 float4 per embedding row
#define PROJ_STRIDE 8       // padded floats per vocab entry (32 B aligned)
#define GRID  592           // 148 SMs x 4 CTAs co-resident (regs forced <=64)
#define NTILES ((VOCAB + 3) / 4)   // 12565 four-row tiles
#define WPAD  41            // 8*5 + 1 float4: bank-conflict-free W layout

// Device scratch (mallocs forbidden). Counters zero at load and reset
// in-kernel every call -> graph-replay safe.
__device__ float        g_proj[(size_t)VOCAB * PROJ_STRIDE];  // ~1.6 MB
__device__ float        g_loss[BATCH];
__device__ unsigned int g_arrive;   // grid-barrier arrivals
__device__ unsigned int g_done;     // grid-barrier departures (guards reset)
__device__ unsigned int g_count;    // CTA completions for final mean

__device__ __forceinline__ float dot4(const float4& a, const float4& b) {
    return a.x * b.x + a.y * b.y + a.z * b.z + a.w * b.w;
}

// 256-bit load with L2 evict_last (sm_103 requires v8.b32 for this hint).
// Pins emb in L2 across graph replays; 32 B/lane/issue.
__device__ __forceinline__ void ldg_el8(const float* p, float4& a, float4& b) {
    unsigned int r0, r1, r2, r3, r4, r5, r6, r7;
    asm("ld.global.L2::evict_last.v8.b32 {%0,%1,%2,%3,%4,%5,%6,%7}, [%8];"
        : "=r"(r0), "=r"(r1), "=r"(r2), "=r"(r3),
          "=r"(r4), "=r"(r5), "=r"(r6), "=r"(r7)
        : "l"(p));
    a = make_float4(__uint_as_float(r0), __uint_as_float(r1),
                    __uint_as_float(r2), __uint_as_float(r3));
    b = make_float4(__uint_as_float(r4), __uint_as_float(r5),
                    __uint_as_float(r6), __uint_as_float(r7));
}

__global__ __launch_bounds__(256, 4)
void fused_kernel(const int*   __restrict__ input_x,
                  const int*   __restrict__ lengths,
                  const int*   __restrict__ input_y,
                  const float* __restrict__ emb,
                  const float* __restrict__ W,
                  const float* __restrict__ bias,
                  float*       __restrict__ out)
{
    __shared__ float4 s_W[8 * WPAD];    // padded: [seg][k][o] -> seg*41+k*5+o
    __shared__ float  s_red[8][OUTC];
    __shared__ float  s_sum[256];
    __shared__ int    s_last;

    const int tid  = threadIdx.x;
    const int lane = tid & 31;
    const int wid  = tid >> 5;

    // Stage W: s_W[seg*41 + k*5 + o] = W[o][seg*8+k]  (320 entries, looped)
    {
        const float4* __restrict__ Wv = (const float4*)W;
        for (int i = tid; i < OUTC * 64; i += 256) {
            const int o  = i >> 6;
            const int c4 = i & 63;
            const int sg = c4 >> 3;
            const int k  = c4 & 7;
            s_W[sg * WPAD + k * 5 + o] = Wv[o * 64 + c4];
        }
    }
    __syncthreads();

    // ====== Phase 1: proj = emb . W^T, 4 rows per warp-tile ================
    // lane -> (rloc = lane>>3, seg = lane&7). Lane owns the CONTIGUOUS 128 B
    // slice [seg*128, seg*128+128) of its row -> 4x 32B-aligned v8 loads.
    {
        const int nwarps = GRID * 8;                 // 4736
        const int gw     = (blockIdx.x << 3) + wid;
        const int rloc   = lane >> 3;                // 0..3
        const int seg    = lane & 7;                 // 0..7

        for (int tile = gw; tile < NTILES; tile += nwarps) {  // warp-uniform
            const int  row   = tile * 4 + rloc;
            const bool valid = row < VOCAB;
            const int  rowc  = valid ? row : (VOCAB - 1);     // clamp (shfl-safe)
            const float* base = emb + (long)rowc * EMBED + seg * 32;

            // Front-batch the lane's 4 x 256-bit loads (evict_last)
            float4 e[8];
            ldg_el8(base,      e[0], e[1]);
            ldg_el8(base + 8,  e[2], e[3]);
            ldg_el8(base + 16, e[4], e[5]);
            ldg_el8(base + 24, e[6], e[7]);

            float acc[OUTC];
            #pragma unroll
            for (int o = 0; o < OUTC; o++) acc[o] = 0.f;

            #pragma unroll
            for (int k = 0; k < 8; k++) {
                const float4* wp = &s_W[seg * WPAD + k * 5];
                acc[0] += dot4(e[k], wp[0]);
                acc[1] += dot4(e[k], wp[1]);
                acc[2] += dot4(e[k], wp[2]);
                acc[3] += dot4(e[k], wp[3]);
                acc[4] += dot4(e[k], wp[4]);
            }

            // Reduce across the 8-lane segment group (all lanes converged)
            #pragma unroll
            for (int o = 0; o < OUTC; o++) {
                acc[o] += __shfl_xor_sync(0xffffffffu, acc[o], 4);
                acc[o] += __shfl_xor_sync(0xffffffffu, acc[o], 2);
                acc[o] += __shfl_xor_sync(0xffffffffu, acc[o], 1);
            }

            if (valid && seg == 0) {
                *(float4*)&g_proj[(long)row * PROJ_STRIDE] =
                    make_float4(acc[0], acc[1], acc[2], acc[3]);
                g_proj[(long)row * PROJ_STRIDE + 4] = acc[4];
            }
        }
    }

    // ====== Grid-wide barrier (592 CTAs co-resident at occ 4) ==============
    __threadfence();            // release g_proj
    __syncthreads();
    if (tid == 0) {
        atomicAdd(&g_arrive, 1u);
        while (*(volatile unsigned int*)&g_arrive < GRID) __nanosleep(64);
        if (atomicAdd(&g_done, 1u) == GRID - 1) {   // all passed the spin
            g_arrive = 0;
            g_done   = 0;
        }
    }
    __syncthreads();
    __threadfence();            // acquire g_proj

    // ====== Phase 2: per-sample loss (CTAs 0..511) =========================
    if (blockIdx.x < BATCH) {
        const int b   = blockIdx.x;
        const int len = lengths[b];
        const int* xrow = input_x + b * SEQ;

        float acc[OUTC];
        #pragma unroll
        for (int o = 0; o < OUTC; o++) acc[o] = 0.f;

        if (tid < len) {
            const int t = xrow[tid];
            float4 p = *(const float4*)&g_proj[(long)t * PROJ_STRIDE];
            float  q = g_proj[(long)t * PROJ_STRIDE + 4];
            acc[0] += p.x; acc[1] += p.y; acc[2] += p.z; acc[3] += p.w; acc[4] += q;
        }
        if (tid + 256 < len) {
            const int t = xrow[tid + 256];
            float4 p = *(const float4*)&g_proj[(long)t * PROJ_STRIDE];
            float  q = g_proj[(long)t * PROJ_STRIDE + 4];
            acc[0] += p.x; acc[1] += p.y; acc[2] += p.z; acc[3] += p.w; acc[4] += q;
        }

        #pragma unroll
        for (int o = 0; o < OUTC; o++) {
            #pragma unroll
            for (int off = 16; off > 0; off >>= 1)
                acc[o] += __shfl_down_sync(0xffffffffu, acc[o], off);
        }
        if (lane == 0) {
            #pragma unroll
            for (int o = 0; o < OUTC; o++) s_red[wid][o] = acc[o];
        }
        __syncthreads();

        if (tid == 0) {
            float tot[OUTC];
            #pragma unroll
            for (int o = 0; o < OUTC; o++) {
                tot[o] = ((s_red[0][o] + s_red[1][o]) + (s_red[2][o] + s_red[3][o]))
                       + ((s_red[4][o] + s_red[5][o]) + (s_red[6][o] + s_red[7][o]));
            }
            const float inv_len = 1.0f / (float)len;
            float logits[OUTC];
            float m = -INFINITY;
            #pragma unroll
            for (int o = 0; o < OUTC; o++) {
                logits[o] = tot[o] * inv_len + bias[o];
                m = fmaxf(m, logits[o]);
            }
            float se = 0.f;
            #pragma unroll
            for (int o = 0; o < OUTC; o++) se += __expf(logits[o] - m);
            const float lse = m + __logf(se);
            const int y = input_y[b];
            g_loss[b] = lse - logits[y];
        }
    }

    // ====== Final mean via last-CTA pattern ================================
    __syncthreads();
    if (tid == 0) {
        __threadfence();
        s_last = (atomicAdd(&g_count, 1u) == GRID - 1) ? 1 : 0;
    }
    __syncthreads();

    if (s_last) {
        __threadfence();
        s_sum[tid] = g_loss[tid] + g_loss[tid + 256];
        __syncthreads();
        #pragma unroll
        for (int off = 128; off > 0; off >>= 1) {
            if (tid < off) s_sum[tid] += s_sum[tid + off];
            __syncthreads();
        }
        if (tid == 0) {
            out[0] = s_sum[0] * (1.0f / (float)BATCH);
            g_count = 0;   // reset for next replay
        }
    }
}

extern "C" void kernel_launch(void* const* d_in, const int* in_sizes, int n_in,
                              void* d_out, int out_size)
{
    const int*   input_x = (const int*)d_in[0];
    const int*   lengths = (const int*)d_in[1];
    const int*   input_y = (const int*)d_in[2];
    const float* emb     = (const float*)d_in[3];
    const float* W       = (const float*)d_in[4];
    const float* bias    = (const float*)d_in[5];
    float* out = (float*)d_out;

    fused_kernel<<<GRID, 256>>>(input_x, lengths, input_y, emb, W, bias, out);
}

// round 16
// speedup vs baseline: 2.5701x; 2.5701x over previous
#include <cuda_runtime.h>
#include <math.h>

#define VOCAB 50257
#define BATCH 512
#define SEQ   512
#define EMBED 256
#define OUTC  5
#define EV4   (EMBED / 4)          // 64 float4 per embedding row
#define CH    4                    // 128-token chunks per sample
#define CHTOK (SEQ / CH)           // 128
#define TOTAL_UNITS (BATCH * CH)   // 2048 work units
#define GRID  592                  // 148 SMs x 4 CTAs, all co-resident

// Device scratch (mallocs forbidden). Counters zero at load and reset
// in-kernel every call -> graph-replay safe.
__device__ float        g_part5[TOTAL_UNITS * 8];  // 5 floats/unit, padded
__device__ float        g_loss[BATCH];
__device__ unsigned int g_next;                    // work-queue ticket
__device__ unsigned int g_scnt[BATCH];             // per-sample chunk counters
__device__ unsigned int g_count;                   // sample completions

__device__ __forceinline__ void acc4(float4& a, const float4& v) {
    a.x += v.x; a.y += v.y; a.z += v.z; a.w += v.w;
}

__global__ __launch_bounds__(256, 4)
void pool_loss_kernel(const int*   __restrict__ input_x,
                      const int*   __restrict__ lengths,
                      const int*   __restrict__ input_y,
                      const float* __restrict__ emb,
                      const float* __restrict__ W,
                      const float* __restrict__ bias,
                      float*       __restrict__ out)
{
    __shared__ int    s_idx[CHTOK];
    __shared__ float4 s_acc[256];
    __shared__ float  s_red[OUTC][2];
    __shared__ float  s_sum[256];
    __shared__ int    s_u, s_flag, s_last;

    const int tid = threadIdx.x;
    const int g   = tid >> 6;   // token group 0..3
    const int l   = tid & 63;   // float4 lane within row

    const float4* __restrict__ embv = (const float4*)emb;

    while (true) {
        // -------- pull next unit from the global queue --------
        if (tid == 0) s_u = (int)atomicAdd(&g_next, 1u);
        __syncthreads();
        const int u = s_u;
        if (u >= TOTAL_UNITS) break;            // uniform exit

        const int b    = u >> 2;
        const int c    = u & 3;
        const int len  = lengths[b];
        const int base = c * CHTOK;
        int count = len - base;
        if (count < 0)     count = 0;
        if (count > CHTOK) count = CHTOK;

        // Stage this chunk's token ids (one coalesced 512 B segment)
        if (tid < count) s_idx[tid] = input_x[b * SEQ + base + tid];
        __syncthreads();

        // -------- R2's gather loop (4 independent LDG.128 in flight) ------
        float4 a0 = make_float4(0.f, 0.f, 0.f, 0.f);
        float4 a1 = make_float4(0.f, 0.f, 0.f, 0.f);
        float4 a2 = make_float4(0.f, 0.f, 0.f, 0.f);
        float4 a3 = make_float4(0.f, 0.f, 0.f, 0.f);

        int s = g;
        for (; s + 12 < count; s += 16) {
            const int t0 = s_idx[s];
            const int t1 = s_idx[s + 4];
            const int t2 = s_idx[s + 8];
            const int t3 = s_idx[s + 12];
            float4 v0 = embv[(long)t0 * EV4 + l];
            float4 v1 = embv[(long)t1 * EV4 + l];
            float4 v2 = embv[(long)t2 * EV4 + l];
            float4 v3 = embv[(long)t3 * EV4 + l];
            acc4(a0, v0); acc4(a1, v1); acc4(a2, v2); acc4(a3, v3);
        }
        for (; s < count; s += 4) {
            const int t = s_idx[s];
            float4 v = embv[(long)t * EV4 + l];
            acc4(a0, v);
        }
        acc4(a0, a1); acc4(a2, a3); acc4(a0, a2);

        s_acc[tid] = a0;
        __syncthreads();

        // -------- combine groups; reduce partial pooled to 5 floats -------
        if (tid < 64) {
            float4 p0 = s_acc[l];
            float4 p1 = s_acc[64 + l];
            float4 p2 = s_acc[128 + l];
            float4 p3 = s_acc[192 + l];
            float4 pooled;
            pooled.x = (p0.x + p1.x) + (p2.x + p3.x);
            pooled.y = (p0.y + p1.y) + (p2.y + p3.y);
            pooled.z = (p0.z + p1.z) + (p2.z + p3.z);
            pooled.w = (p0.w + p1.w) + (p2.w + p3.w);

            const float4* __restrict__ Wv = (const float4*)W;
            float part[OUTC];
            #pragma unroll
            for (int o = 0; o < OUTC; o++) {
                float4 w = Wv[o * EV4 + l];
                part[o] = pooled.x * w.x + pooled.y * w.y
                        + pooled.z * w.z + pooled.w * w.w;
            }
            #pragma unroll
            for (int o = 0; o < OUTC; o++) {
                float v = part[o];
                #pragma unroll
                for (int off = 16; off > 0; off >>= 1)
                    v += __shfl_down_sync(0xffffffffu, v, off);
                part[o] = v;
            }
            if ((tid & 31) == 0) {
                const int w = tid >> 5;   // 0 or 1
                #pragma unroll
                for (int o = 0; o < OUTC; o++) s_red[o][w] = part[o];
            }
        }
        __syncthreads();

        // -------- publish 5-float partial; count chunk completion ---------
        if (tid == 0) {
            #pragma unroll
            for (int o = 0; o < OUTC; o++)
                g_part5[u * 8 + o] = s_red[o][0] + s_red[o][1];
            __threadfence();
            s_flag = (atomicAdd(&g_scnt[b], 1u) == CH - 1) ? 1 : 0;
        }
        __syncthreads();

        // -------- last chunk of sample b: finalize loss -------------------
        if (s_flag) {
            if (tid == 0) {
                g_scnt[b] = 0;                 // reset for next replay
                __threadfence();               // order partial reads
                float tot[OUTC];
                #pragma unroll
                for (int o = 0; o < OUTC; o++) {
                    // Fixed combine order -> bit-deterministic
                    tot[o] = (g_part5[(b * 4 + 0) * 8 + o]
                            + g_part5[(b * 4 + 1) * 8 + o])
                           + (g_part5[(b * 4 + 2) * 8 + o]
                            + g_part5[(b * 4 + 3) * 8 + o]);
                }
                const float inv_len = 1.0f / (float)len;
                float logits[OUTC];
                float m = -INFINITY;
                #pragma unroll
                for (int o = 0; o < OUTC; o++) {
                    logits[o] = tot[o] * inv_len + bias[o];
                    m = fmaxf(m, logits[o]);
                }
                float se = 0.f;
                #pragma unroll
                for (int o = 0; o < OUTC; o++) se += __expf(logits[o] - m);
                const float lse = m + __logf(se);
                const int y = input_y[b];
                g_loss[b] = lse - logits[y];
                __threadfence();
                s_last = (atomicAdd(&g_count, 1u) == BATCH - 1) ? 1 : 0;
            }
            __syncthreads();

            // -------- globally last finalizer: mean over 512 losses -------
            if (s_last) {
                __threadfence();
                s_sum[tid] = g_loss[tid] + g_loss[tid + 256];
                __syncthreads();
                #pragma unroll
                for (int off = 128; off > 0; off >>= 1) {
                    if (tid < off) s_sum[tid] += s_sum[tid + off];
                    __syncthreads();
                }
                if (tid == 0) {
                    out[0] = s_sum[0] * (1.0f / (float)BATCH);
                    g_count = 0;               // reset for next replay
                }
            }
        }
        __syncthreads();   // protect smem reuse before next pull
    }

    // Exactly TOTAL_UNITS + GRID pulls occur (one failing pull per CTA).
    // The CTA holding the last ticket resets the queue for the next replay.
    if (tid == 0 && s_u == TOTAL_UNITS + GRID - 1) g_next = 0;
}

extern "C" void kernel_launch(void* const* d_in, const int* in_sizes, int n_in,
                              void* d_out, int out_size)
{
    const int*   input_x = (const int*)d_in[0];
    const int*   lengths = (const int*)d_in[1];
    const int*   input_y = (const int*)d_in[2];
    const float* emb     = (const float*)d_in[3];
    const float* W       = (const float*)d_in[4];
    const float* bias    = (const float*)d_in[5];
    float* out = (float*)d_out;

    pool_loss_kernel<<<GRID, 256>>>(input_x, lengths, input_y, emb, W, bias, out);
}